// round 9
// baseline (speedup 1.0000x reference)
#include <cuda_runtime.h>
#include <cuda_fp16.h>
#include <cstdint>

#define C_TOT 256
#define H_TOT 56
#define W_TOT 56
#define HW    3136
#define M_TOT 100352   // 32*56*56
#define CI    1024

// ---------------- scratch (static device globals; no allocations) ----------
__device__ __half g_y[(size_t)M_TOT * C_TOT];   // NHWC, BN'd, fp16
__device__ __half g_h[(size_t)M_TOT * CI];      // GELU output, fp16
__device__ __half g_w1[CI * C_TOT];             // fc1_w fp16
__device__ __half g_w2[C_TOT * CI];             // fc2_w fp16

__device__ __forceinline__ float gelu_exact(float v) {
    return 0.5f * v * (1.0f + erff(v * 0.70710678118654752440f));
}

// ---------------- kernel 1: round weights to fp16 --------------------------
__global__ void convert_weights_kernel(const float* __restrict__ fc1,
                                       const float* __restrict__ fc2) {
    int i = blockIdx.x * blockDim.x + threadIdx.x;
    if (i < CI * C_TOT) {
        g_w1[i] = __float2half_rn(fc1[i]);
        g_w2[i] = __float2half_rn(fc2[i]);
    }
}

// ---------------- kernel 2: NeoCell + BN -> y (NHWC, fp16) ------------------
__global__ __launch_bounds__(256)
void neocell_bn_kernel(const float* __restrict__ x,
                       const float* __restrict__ wa1, const float* __restrict__ wb1,
                       const float* __restrict__ wa2, const float* __restrict__ wb2,
                       const float* __restrict__ bnw, const float* __restrict__ bnb,
                       const float* __restrict__ bnm, const float* __restrict__ bnv) {
    __shared__ float tile[32 * 229];
    const int hs = blockIdx.x;
    const int c0 = blockIdx.y * 32;
    const int b  = blockIdx.z;
    const int h0 = hs * 4;

    const float* xb = x + ((size_t)b * C_TOT + c0) * HW + (size_t)h0 * W_TOT;
    for (int idx = threadIdx.x; idx < 32 * 4 * 56; idx += 256) {
        int c = idx / 224, r = idx % 224;
        int hh = r / 56, w = r % 56;
        tile[c * 229 + hh * 57 + w] = xb[(size_t)c * HW + hh * W_TOT + w];
    }
    __syncthreads();

    const int t  = threadIdx.x;
    const int c  = t & 31;
    const int s  = t >> 5;
    const int gc = c0 + c;
    const float scale = bnw[gc] * rsqrtf(bnv[gc] + 1e-5f);
    const float shift = bnb[gc] - bnm[gc] * scale;
    __half* ybase = g_y + ((size_t)b * H_TOT + h0) * W_TOT * C_TOT + gc;
    const float* tc = tile + c * 229;

    if (gc < 128) {
        const float a00 = wa1[gc*4+0], a01 = wa1[gc*4+1], a10 = wa1[gc*4+2], a11 = wa1[gc*4+3];
        const float b00 = wb1[gc*4+0], b01 = wb1[gc*4+1], b10 = wb1[gc*4+2], b11 = wb1[gc*4+3];
        for (int bi = s; bi < 56; bi += 8) {
            int n = bi / 28, m = bi % 28;
            const float* tp = tc + n * 2 * 57 + m * 2;
            float x00 = tp[0],  x01 = tp[1];
            float x10 = tp[57], x11 = tp[58];
            float t00 = a00 * x00 + a01 * x10;
            float t01 = a00 * x01 + a01 * x11;
            float t10 = a10 * x00 + a11 * x10;
            float t11 = a10 * x01 + a11 * x11;
            float y00 = t00 * b00 + t01 * b10;
            float y01 = t00 * b01 + t01 * b11;
            float y10 = t10 * b00 + t11 * b10;
            float y11 = t10 * b01 + t11 * b11;
            size_t base = ((size_t)(n * 2) * 56 + m * 2) * (size_t)C_TOT;
            ybase[base]            = __float2half_rn(y00 * scale + shift);
            ybase[base + 256]      = __float2half_rn(y01 * scale + shift);
            ybase[base + 56 * 256] = __float2half_rn(y10 * scale + shift);
            ybase[base + 57 * 256] = __float2half_rn(y11 * scale + shift);
        }
    } else {
        const float* wap = wa2 + (size_t)(gc - 128) * 16;
        const float* wbp = wb2 + (size_t)(gc - 128) * 16;
        float a[4][4], bw[4][4];
        #pragma unroll
        for (int i = 0; i < 4; i++)
            #pragma unroll
            for (int j = 0; j < 4; j++) { a[i][j] = wap[i*4+j]; bw[i][j] = wbp[i*4+j]; }
        for (int m = s; m < 14; m += 8) {
            float xv[4][4];
            #pragma unroll
            for (int i = 0; i < 4; i++)
                #pragma unroll
                for (int j = 0; j < 4; j++) xv[i][j] = tc[i * 57 + m * 4 + j];
            float tv[4][4];
            #pragma unroll
            for (int p = 0; p < 4; p++)
                #pragma unroll
                for (int j = 0; j < 4; j++)
                    tv[p][j] = a[p][0]*xv[0][j] + a[p][1]*xv[1][j]
                             + a[p][2]*xv[2][j] + a[p][3]*xv[3][j];
            #pragma unroll
            for (int p = 0; p < 4; p++)
                #pragma unroll
                for (int q = 0; q < 4; q++) {
                    float v = tv[p][0]*bw[0][q] + tv[p][1]*bw[1][q]
                            + tv[p][2]*bw[2][q] + tv[p][3]*bw[3][q];
                    ybase[((size_t)(p * 56) + m * 4 + q) * (size_t)C_TOT] =
                        __float2half_rn(v * scale + shift);
                }
        }
    }
}

// ---------------- GEMM (TN: C[m,n] = sum_k A[m,k]*B[n,k]), fp16 mma --------
// CTA tile 128x128, BK=32 halves, 4 warps (2m x 2n), warp tile 64x64, k16 steps.
// XOR-swizzled 64B smem rows (no pad), 4-stage cp.async ring, 1 barrier/iter.
#define BKH        32                   // halves per k-tile (64 B rows)
#define ROWB       64                   // bytes per smem row
#define A_STG      (128 * ROWB)         // 8192 B per matrix per stage
#define STG_B      (2 * A_STG)          // 16384 B per stage (A + B)
#define NSTAGE     4
#define GSMEM      (NSTAGE * STG_B)     // 65536 B

template<int K, int MODE>
__global__ __launch_bounds__(128, 2)
void gemm_tn_kernel(float* __restrict__ outp, const float* __restrict__ xres) {
    extern __shared__ __align__(16) __half sm[];
    const __half* Amat = (MODE == 1) ? g_y : g_h;
    const __half* Bmat = (MODE == 1) ? g_w1 : g_w2;
    constexpr int KT = K / BKH;

    const int tid  = threadIdx.x;
    const int lane = tid & 31;
    const int warp = tid >> 5;
    const int wm   = warp & 1;          // 2 m-warps (64 rows each)
    const int wn   = warp >> 1;         // 2 n-warps (64 cols each)
    const int bm   = blockIdx.y * 128;
    const int bn   = blockIdx.x * 128;

    // global -> smem staging: 4 threads per row (32 halves), 32 rows/pass
    const int lrow = tid >> 2;          // 0..31
    const int lck  = tid & 3;           // 16B chunk within 64B row
    const int swc  = lck ^ ((lrow >> 1) & 3);   // swizzled chunk (pass-invariant)
    const __half* Ap = Amat + (size_t)(bm + lrow) * K + lck * 8;
    const __half* Bp = Bmat + (size_t)(bn + lrow) * K + lck * 8;

    const uint32_t smb = (uint32_t)__cvta_generic_to_shared(sm);
    const uint32_t sa  = smb + (uint32_t)(lrow * ROWB + swc * 16);
    const uint32_t sb  = sa + (uint32_t)A_STG;

    float acc[4][8][4];
    #pragma unroll
    for (int i = 0; i < 4; i++)
        #pragma unroll
        for (int j = 0; j < 8; j++)
            #pragma unroll
            for (int q = 0; q < 4; q++) acc[i][j][q] = 0.f;

    // ldmatrix addressing: lane -> (row = lane%15, 16B col-half = lane/16),
    // swizzled chunk = (2s + hi) ^ ((row>>1)&3)  (constant per lane per substep)
    const int xrow = lane & 15;
    const int hi   = lane >> 4;
    const int csw  = (xrow >> 1) & 3;
    const uint32_t xb0 = (uint32_t)(((hi)     ^ csw) * 16);   // substep 0
    const uint32_t xb1 = (uint32_t)(((2 + hi) ^ csw) * 16);   // substep 1
    const uint32_t abase = smb + (uint32_t)((wm * 64 + xrow) * ROWB);
    const uint32_t bbase = smb + (uint32_t)(A_STG + (wn * 64 + xrow) * ROWB);

#define PREFETCH(ktv, stv) do {                                                          \
    const __half* ap_ = Ap + (ktv) * BKH;                                                \
    const __half* bp_ = Bp + (ktv) * BKH;                                                \
    uint32_t so_ = (uint32_t)((stv) * STG_B);                                            \
    _Pragma("unroll")                                                                    \
    for (int rp_ = 0; rp_ < 4; rp_++) {                                                  \
        asm volatile("cp.async.cg.shared.global [%0], [%1], 16;\n"                       \
                     :: "r"(sa + so_ + (uint32_t)(rp_ * 32 * ROWB)),                     \
                        "l"(ap_ + (size_t)(rp_ * 32) * K));                              \
        asm volatile("cp.async.cg.shared.global [%0], [%1], 16;\n"                       \
                     :: "r"(sb + so_ + (uint32_t)(rp_ * 32 * ROWB)),                     \
                        "l"(bp_ + (size_t)(rp_ * 32) * K));                              \
    }                                                                                    \
    asm volatile("cp.async.commit_group;\n");                                            \
} while (0)

#define LDSM(dst, addr)                                                                  \
    asm volatile("ldmatrix.sync.aligned.m8n8.x4.shared.b16 {%0,%1,%2,%3}, [%4];\n"       \
        : "=r"((dst)[0]), "=r"((dst)[1]), "=r"((dst)[2]), "=r"((dst)[3]) : "r"(addr))

#define MMA16(accj, afr, b0, b1)                                                         \
    asm volatile("mma.sync.aligned.m16n8k16.row.col.f32.f16.f16.f32 "                    \
        "{%0,%1,%2,%3}, {%4,%5,%6,%7}, {%8,%9}, {%0,%1,%2,%3};\n"                        \
        : "+f"((accj)[0]), "+f"((accj)[1]), "+f"((accj)[2]), "+f"((accj)[3])             \
        : "r"((afr)[0]), "r"((afr)[1]), "r"((afr)[2]), "r"((afr)[3]),                    \
          "r"(b0), "r"(b1))

    // prologue: fill stages 0..2
    PREFETCH(0, 0);
    PREFETCH(1, 1);
    PREFETCH(2, 2);

    for (int kt = 0; kt < KT; ++kt) {
        const int st = kt & (NSTAGE - 1);
        if (kt + 2 < KT)      asm volatile("cp.async.wait_group 2;\n");
        else if (kt + 1 < KT) asm volatile("cp.async.wait_group 1;\n");
        else                  asm volatile("cp.async.wait_group 0;\n");
        __syncthreads();
        if (kt + 3 < KT) PREFETCH(kt + 3, (kt + 3) & (NSTAGE - 1));

        const uint32_t soff = (uint32_t)(st * STG_B);
        #pragma unroll
        for (int s = 0; s < 2; s++) {             // two k16 sub-steps per BK=32
            const uint32_t xb = soff + (s ? xb1 : xb0);
            uint32_t af[4][4];
            #pragma unroll
            for (int mt = 0; mt < 4; mt++)
                LDSM(af[mt], abase + xb + (uint32_t)(mt * 16 * ROWB));
            uint32_t bf[4][4];
            #pragma unroll
            for (int p = 0; p < 4; p++)
                LDSM(bf[p], bbase + xb + (uint32_t)(p * 16 * ROWB));
            // one B ldmatrix.x4 covers two adjacent n8 tiles: {r0,r2} and {r1,r3}
            #pragma unroll
            for (int p = 0; p < 4; p++)
                #pragma unroll
                for (int mt = 0; mt < 4; mt++) {
                    MMA16(acc[mt][2*p],   af[mt], bf[p][0], bf[p][2]);
                    MMA16(acc[mt][2*p+1], af[mt], bf[p][1], bf[p][3]);
                }
        }
    }
#undef PREFETCH
#undef LDSM
#undef MMA16

    if (MODE == 1) {
        // GELU, round to fp16, store h [M x 1024]
        #pragma unroll
        for (int mt = 0; mt < 4; mt++) {
            const int r0 = bm + wm * 64 + mt * 16 + (lane >> 2);
            #pragma unroll
            for (int j = 0; j < 8; j++) {
                const int nc = bn + wn * 64 + j * 8 + (lane & 3) * 2;
                __half2* p0 = (__half2*)(g_h + (size_t)r0 * CI + nc);
                __half2* p1 = (__half2*)(g_h + (size_t)(r0 + 8) * CI + nc);
                *p0 = __floats2half2_rn(gelu_exact(acc[mt][j][0]), gelu_exact(acc[mt][j][1]));
                *p1 = __floats2half2_rn(gelu_exact(acc[mt][j][2]), gelu_exact(acc[mt][j][3]));
            }
        }
    } else {
        // residual + NCHW store (per-column 8-row runs -> full 32B sectors)
        #pragma unroll
        for (int mt = 0; mt < 4; mt++) {
            const int r0 = bm + wm * 64 + mt * 16 + (lane >> 2);
            const int r1 = r0 + 8;
            const int b0 = r0 / HW, hw0 = r0 - b0 * HW;
            const int b1 = r1 / HW, hw1 = r1 - b1 * HW;
            const size_t base0 = (size_t)b0 * C_TOT * HW + hw0;
            const size_t base1 = (size_t)b1 * C_TOT * HW + hw1;
            #pragma unroll
            for (int j = 0; j < 8; j++) {
                const int nc = bn + wn * 64 + j * 8 + (lane & 3) * 2;
                size_t i0 = base0 + (size_t)nc * HW;
                outp[i0]      = acc[mt][j][0] + xres[i0];
                outp[i0 + HW] = acc[mt][j][1] + xres[i0 + HW];
                size_t i1 = base1 + (size_t)nc * HW;
                outp[i1]      = acc[mt][j][2] + xres[i1];
                outp[i1 + HW] = acc[mt][j][3] + xres[i1 + HW];
            }
        }
    }
}

// ---------------- launch ----------------------------------------------------
extern "C" void kernel_launch(void* const* d_in, const int* in_sizes, int n_in,
                              void* d_out, int out_size) {
    const float* x   = (const float*)d_in[0];
    const float* wa1 = (const float*)d_in[1];
    const float* wb1 = (const float*)d_in[2];
    const float* wa2 = (const float*)d_in[3];
    const float* wb2 = (const float*)d_in[4];
    const float* bnw = (const float*)d_in[5];
    const float* bnb = (const float*)d_in[6];
    const float* bnm = (const float*)d_in[7];
    const float* bnv = (const float*)d_in[8];
    const float* fc1 = (const float*)d_in[9];
    const float* fc2 = (const float*)d_in[10];
    float* out = (float*)d_out;

    cudaFuncSetAttribute(gemm_tn_kernel<256, 1>,
                         cudaFuncAttributeMaxDynamicSharedMemorySize, GSMEM);
    cudaFuncSetAttribute(gemm_tn_kernel<1024, 2>,
                         cudaFuncAttributeMaxDynamicSharedMemorySize, GSMEM);

    convert_weights_kernel<<<(CI * C_TOT + 255) / 256, 256>>>(fc1, fc2);
    neocell_bn_kernel<<<dim3(14, 8, 32), 256>>>(x, wa1, wb1, wa2, wb2,
                                                bnw, bnb, bnm, bnv);
    gemm_tn_kernel<256, 1><<<dim3(8, 784), 128, GSMEM>>>(nullptr, nullptr);   // y @ fc1^T, GELU
    gemm_tn_kernel<1024, 2><<<dim3(2, 784), 128, GSMEM>>>(out, x);            // h @ fc2^T + x
}

// round 11
// speedup vs baseline: 1.0414x; 1.0414x over previous
#include <cuda_runtime.h>
#include <cuda_fp16.h>
#include <cstdint>

#define C_TOT 256
#define H_TOT 56
#define W_TOT 56
#define HW    3136
#define M_TOT 100352   // 32*56*56
#define CI    1024

// ---------------- scratch (static device globals; no allocations) ----------
__device__ __half g_y[(size_t)M_TOT * C_TOT];   // NHWC, BN'd, fp16
__device__ __half g_h[(size_t)M_TOT * CI];      // GELU output, fp16
__device__ __half g_w1[CI * C_TOT];             // fc1_w fp16
__device__ __half g_w2[C_TOT * CI];             // fc2_w fp16

__device__ __forceinline__ float gelu_exact(float v) {
    return 0.5f * v * (1.0f + erff(v * 0.70710678118654752440f));
}

// ---------------- kernel 1: round weights to fp16 --------------------------
__global__ void convert_weights_kernel(const float* __restrict__ fc1,
                                       const float* __restrict__ fc2) {
    int i = blockIdx.x * blockDim.x + threadIdx.x;
    if (i < CI * C_TOT) {
        g_w1[i] = __float2half_rn(fc1[i]);
        g_w2[i] = __float2half_rn(fc2[i]);
    }
}

// ---------------- kernel 2: NeoCell + BN -> y (NHWC fp16, coalesced) --------
// CTA: batch b, 4x8 spatial patch, ALL 256 channels. thread = channel.
// smem xs[32 pixels][257] f32 (load, transpose); reused as ys[32][256] fp16.
// Output written as contiguous 512B pixel rows (full sectors).
__global__ __launch_bounds__(256)
void neocell_bn_kernel(const float* __restrict__ x,
                       const float* __restrict__ wa1, const float* __restrict__ wb1,
                       const float* __restrict__ wa2, const float* __restrict__ wb2,
                       const float* __restrict__ bnw, const float* __restrict__ bnb,
                       const float* __restrict__ bnm, const float* __restrict__ bnv) {
    __shared__ float xs[32][257];
    const int bh = blockIdx.x;        // 0..13 (4-row strip)
    const int bw = blockIdx.y;        // 0..6  (8-col group)
    const int b  = blockIdx.z;
    const int h0 = bh * 4, w0 = bw * 8;
    const int tid = threadIdx.x;

    // load: idx = tid + p*256; one warp handles one channel's 32 pixels
    const float* xb = x + (size_t)b * C_TOT * HW;
    #pragma unroll 4
    for (int p = 0; p < 32; p++) {
        int idx = tid + p * 256;
        int c = idx >> 5, r = idx & 31;
        int h = r >> 3, w = r & 7;
        xs[r][c] = xb[(size_t)c * HW + (h0 + h) * W_TOT + w0 + w];
    }
    __syncthreads();

    const int c = tid;
    const float scale = bnw[c] * rsqrtf(bnv[c] + 1e-5f);
    const float shift = bnb[c] - bnm[c] * scale;
    __half2 yv[16];                   // pixel pairs (2q, 2q+1), this channel

    if (c < 128) {
        const float a00 = wa1[c*4+0], a01 = wa1[c*4+1], a10 = wa1[c*4+2], a11 = wa1[c*4+3];
        const float b00 = wb1[c*4+0], b01 = wb1[c*4+1], b10 = wb1[c*4+2], b11 = wb1[c*4+3];
        #pragma unroll
        for (int n = 0; n < 2; n++)
            #pragma unroll
            for (int m = 0; m < 4; m++) {
                int r0 = (2*n) * 8 + 2*m;
                float x00 = xs[r0][c],     x01 = xs[r0 + 1][c];
                float x10 = xs[r0 + 8][c], x11 = xs[r0 + 9][c];
                float t00 = a00*x00 + a01*x10, t01 = a00*x01 + a01*x11;
                float t10 = a10*x00 + a11*x10, t11 = a10*x01 + a11*x11;
                float y00 = t00*b00 + t01*b10, y01 = t00*b01 + t01*b11;
                float y10 = t10*b00 + t11*b10, y11 = t10*b01 + t11*b11;
                yv[r0 >> 1]       = __floats2half2_rn(y00*scale+shift, y01*scale+shift);
                yv[(r0 + 8) >> 1] = __floats2half2_rn(y10*scale+shift, y11*scale+shift);
            }
    } else {
        const float* wap = wa2 + (size_t)(c - 128) * 16;
        const float* wbp = wb2 + (size_t)(c - 128) * 16;
        float a[4][4], bwt[4][4];
        #pragma unroll
        for (int i = 0; i < 4; i++)
            #pragma unroll
            for (int j = 0; j < 4; j++) { a[i][j] = wap[i*4+j]; bwt[i][j] = wbp[i*4+j]; }
        #pragma unroll
        for (int v = 0; v < 2; v++) {     // two 4x4 blocks (cols 4v..4v+3)
            float xv[4][4];
            #pragma unroll
            for (int i = 0; i < 4; i++)
                #pragma unroll
                for (int j = 0; j < 4; j++) xv[i][j] = xs[i*8 + 4*v + j][c];
            float tv[4][4];
            #pragma unroll
            for (int p = 0; p < 4; p++)
                #pragma unroll
                for (int j = 0; j < 4; j++)
                    tv[p][j] = a[p][0]*xv[0][j] + a[p][1]*xv[1][j]
                             + a[p][2]*xv[2][j] + a[p][3]*xv[3][j];
            #pragma unroll
            for (int p = 0; p < 4; p++) {
                float y0 = tv[p][0]*bwt[0][0] + tv[p][1]*bwt[1][0] + tv[p][2]*bwt[2][0] + tv[p][3]*bwt[3][0];
                float y1 = tv[p][0]*bwt[0][1] + tv[p][1]*bwt[1][1] + tv[p][2]*bwt[2][1] + tv[p][3]*bwt[3][1];
                float y2 = tv[p][0]*bwt[0][2] + tv[p][1]*bwt[1][2] + tv[p][2]*bwt[2][2] + tv[p][3]*bwt[3][2];
                float y3 = tv[p][0]*bwt[0][3] + tv[p][1]*bwt[1][3] + tv[p][2]*bwt[2][3] + tv[p][3]*bwt[3][3];
                int r0 = p*8 + 4*v;
                yv[r0 >> 1]       = __floats2half2_rn(y0*scale+shift, y1*scale+shift);
                yv[(r0 + 2) >> 1] = __floats2half2_rn(y2*scale+shift, y3*scale+shift);
            }
        }
    }
    __syncthreads();

    // reuse xs as ys[32 pixels][256 ch] fp16
    __half* ys = (__half*)&xs[0][0];
    #pragma unroll
    for (int q = 0; q < 16; q++) {
        ys[(2*q)     * 256 + c] = __low2half(yv[q]);
        ys[(2*q + 1) * 256 + c] = __high2half(yv[q]);
    }
    __syncthreads();

    // write out: 32 pixel rows x 512B, fully coalesced uint4
    __half* yg = g_y + ((size_t)b * HW) * C_TOT;
    #pragma unroll
    for (int k = 0; k < 4; k++) {
        int idx = tid + k * 256;          // 1024 chunks total
        int p = idx >> 5, ch = idx & 31;
        int h = p >> 3, w = p & 7;
        uint4 v = ((const uint4*)ys)[p * 32 + ch];
        *(uint4*)&yg[((size_t)(h0 + h) * W_TOT + w0 + w) * C_TOT + ch * 8] = v;
    }
}

// ---------------- GEMM (TN: C[m,n] = sum_k A[m,k]*B[n,k]), fp16 mma --------
// CTA tile 128x128, BK=32 halves, 4 warps (2m x 2n), warp tile 64x64, k16 steps.
// XOR-swizzled 64B smem rows, 4-stage cp.async ring, 1 barrier/iter.
// MODE1 epilogue: smem-bounce -> coalesced 256B-row h stores.
#define BKH        32
#define ROWB       64
#define A_STG      (128 * ROWB)         // 8192 B per matrix per stage
#define STG_B      (2 * A_STG)          // 16384 B per stage
#define NSTAGE     4
#define GSMEM      (NSTAGE * STG_B)     // 65536 B

template<int K, int MODE>
__global__ __launch_bounds__(128, 2)
void gemm_tn_kernel(float* __restrict__ outp, const float* __restrict__ xres) {
    extern __shared__ __align__(16) __half sm[];
    const __half* Amat = (MODE == 1) ? g_y : g_h;
    const __half* Bmat = (MODE == 1) ? g_w1 : g_w2;
    constexpr int KT = K / BKH;

    const int tid  = threadIdx.x;
    const int lane = tid & 31;
    const int warp = tid >> 5;
    const int wm   = warp & 1;
    const int wn   = warp >> 1;
    const int bm   = blockIdx.y * 128;
    const int bn   = blockIdx.x * 128;

    const int lrow = tid >> 2;
    const int lck  = tid & 3;
    const int swc  = lck ^ ((lrow >> 1) & 3);
    const __half* Ap = Amat + (size_t)(bm + lrow) * K + lck * 8;
    const __half* Bp = Bmat + (size_t)(bn + lrow) * K + lck * 8;

    const uint32_t smb = (uint32_t)__cvta_generic_to_shared(sm);
    const uint32_t sa  = smb + (uint32_t)(lrow * ROWB + swc * 16);
    const uint32_t sb  = sa + (uint32_t)A_STG;

    float acc[4][8][4];
    #pragma unroll
    for (int i = 0; i < 4; i++)
        #pragma unroll
        for (int j = 0; j < 8; j++)
            #pragma unroll
            for (int q = 0; q < 4; q++) acc[i][j][q] = 0.f;

    const int xrow = lane & 15;
    const int hi   = lane >> 4;
    const int csw  = (xrow >> 1) & 3;
    const uint32_t xb0 = (uint32_t)(((hi)     ^ csw) * 16);
    const uint32_t xb1 = (uint32_t)(((2 + hi) ^ csw) * 16);
    const uint32_t abase = smb + (uint32_t)((wm * 64 + xrow) * ROWB);
    const uint32_t bbase = smb + (uint32_t)(A_STG + (wn * 64 + xrow) * ROWB);

#define PREFETCH(ktv, stv) do {                                                          \
    const __half* ap_ = Ap + (ktv) * BKH;                                                \
    const __half* bp_ = Bp + (ktv) * BKH;                                                \
    uint32_t so_ = (uint32_t)((stv) * STG_B);                                            \
    _Pragma("unroll")                                                                    \
    for (int rp_ = 0; rp_ < 4; rp_++) {                                                  \
        asm volatile("cp.async.cg.shared.global [%0], [%1], 16;\n"                       \
                     :: "r"(sa + so_ + (uint32_t)(rp_ * 32 * ROWB)),                     \
                        "l"(ap_ + (size_t)(rp_ * 32) * K));                              \
        asm volatile("cp.async.cg.shared.global [%0], [%1], 16;\n"                       \
                     :: "r"(sb + so_ + (uint32_t)(rp_ * 32 * ROWB)),                     \
                        "l"(bp_ + (size_t)(rp_ * 32) * K));                              \
    }                                                                                    \
    asm volatile("cp.async.commit_group;\n");                                            \
} while (0)

#define LDSM(dst, addr)                                                                  \
    asm volatile("ldmatrix.sync.aligned.m8n8.x4.shared.b16 {%0,%1,%2,%3}, [%4];\n"       \
        : "=r"((dst)[0]), "=r"((dst)[1]), "=r"((dst)[2]), "=r"((dst)[3]) : "r"(addr))

#define MMA16(accj, afr, b0, b1)                                                         \
    asm volatile("mma.sync.aligned.m16n8k16.row.col.f32.f16.f16.f32 "                    \
        "{%0,%1,%2,%3}, {%4,%5,%6,%7}, {%8,%9}, {%0,%1,%2,%3};\n"                        \
        : "+f"((accj)[0]), "+f"((accj)[1]), "+f"((accj)[2]), "+f"((accj)[3])             \
        : "r"((afr)[0]), "r"((afr)[1]), "r"((afr)[2]), "r"((afr)[3]),                    \
          "r"(b0), "r"(b1))

    PREFETCH(0, 0);
    PREFETCH(1, 1);
    PREFETCH(2, 2);

    for (int kt = 0; kt < KT; ++kt) {
        const int st = kt & (NSTAGE - 1);
        if (kt + 2 < KT)      asm volatile("cp.async.wait_group 2;\n");
        else if (kt + 1 < KT) asm volatile("cp.async.wait_group 1;\n");
        else                  asm volatile("cp.async.wait_group 0;\n");
        __syncthreads();
        if (kt + 3 < KT) PREFETCH(kt + 3, (kt + 3) & (NSTAGE - 1));

        const uint32_t soff = (uint32_t)(st * STG_B);
        #pragma unroll
        for (int s = 0; s < 2; s++) {
            const uint32_t xb = soff + (s ? xb1 : xb0);
            uint32_t af[4][4];
            #pragma unroll
            for (int mt = 0; mt < 4; mt++)
                LDSM(af[mt], abase + xb + (uint32_t)(mt * 16 * ROWB));
            uint32_t bf[4][4];
            #pragma unroll
            for (int p = 0; p < 4; p++)
                LDSM(bf[p], bbase + xb + (uint32_t)(p * 16 * ROWB));
            #pragma unroll
            for (int p = 0; p < 4; p++)
                #pragma unroll
                for (int mt = 0; mt < 4; mt++) {
                    MMA16(acc[mt][2*p],   af[mt], bf[p][0], bf[p][2]);
                    MMA16(acc[mt][2*p+1], af[mt], bf[p][1], bf[p][3]);
                }
        }
    }
#undef PREFETCH
#undef LDSM
#undef MMA16

    if (MODE == 1) {
        // GELU -> smem stage (row stride 136 halves, 4-way bank spread) -> coalesced h
        __syncthreads();                       // all warps done reading pipeline smem
        __half2* stg2 = (__half2*)sm;          // row stride = 68 half2 words
        #pragma unroll
        for (int mt = 0; mt < 4; mt++) {
            const int r0 = wm * 64 + mt * 16 + (lane >> 2);
            #pragma unroll
            for (int j = 0; j < 8; j++) {
                const int cw = (wn * 64 + j * 8) / 2 + (lane & 3);
                stg2[r0 * 68 + cw] =
                    __floats2half2_rn(gelu_exact(acc[mt][j][0]), gelu_exact(acc[mt][j][1]));
                stg2[(r0 + 8) * 68 + cw] =
                    __floats2half2_rn(gelu_exact(acc[mt][j][2]), gelu_exact(acc[mt][j][3]));
            }
        }
        __syncthreads();
        #pragma unroll
        for (int k = 0; k < 16; k++) {
            int idx = tid + k * 128;           // 2048 chunks (128 rows x 16)
            int row = idx >> 4, ch = idx & 15;
            uint4 v = *(const uint4*)&sm[row * 136 + ch * 8];
            *(uint4*)&g_h[(size_t)(bm + row) * CI + bn + ch * 8] = v;
        }
    } else {
        // residual + NCHW store (per-column 8-row runs -> full 32B sectors)
        #pragma unroll
        for (int mt = 0; mt < 4; mt++) {
            const int r0 = bm + wm * 64 + mt * 16 + (lane >> 2);
            const int r1 = r0 + 8;
            const int b0 = r0 / HW, hw0 = r0 - b0 * HW;
            const int b1 = r1 / HW, hw1 = r1 - b1 * HW;
            const size_t base0 = (size_t)b0 * C_TOT * HW + hw0;
            const size_t base1 = (size_t)b1 * C_TOT * HW + hw1;
            #pragma unroll
            for (int j = 0; j < 8; j++) {
                const int nc = bn + wn * 64 + j * 8 + (lane & 3) * 2;
                size_t i0 = base0 + (size_t)nc * HW;
                outp[i0]      = acc[mt][j][0] + xres[i0];
                outp[i0 + HW] = acc[mt][j][1] + xres[i0 + HW];
                size_t i1 = base1 + (size_t)nc * HW;
                outp[i1]      = acc[mt][j][2] + xres[i1];
                outp[i1 + HW] = acc[mt][j][3] + xres[i1 + HW];
            }
        }
    }
}

// ---------------- launch ----------------------------------------------------
extern "C" void kernel_launch(void* const* d_in, const int* in_sizes, int n_in,
                              void* d_out, int out_size) {
    const float* x   = (const float*)d_in[0];
    const float* wa1 = (const float*)d_in[1];
    const float* wb1 = (const float*)d_in[2];
    const float* wa2 = (const float*)d_in[3];
    const float* wb2 = (const float*)d_in[4];
    const float* bnw = (const float*)d_in[5];
    const float* bnb = (const float*)d_in[6];
    const float* bnm = (const float*)d_in[7];
    const float* bnv = (const float*)d_in[8];
    const float* fc1 = (const float*)d_in[9];
    const float* fc2 = (const float*)d_in[10];
    float* out = (float*)d_out;

    cudaFuncSetAttribute(gemm_tn_kernel<256, 1>,
                         cudaFuncAttributeMaxDynamicSharedMemorySize, GSMEM);
    cudaFuncSetAttribute(gemm_tn_kernel<1024, 2>,
                         cudaFuncAttributeMaxDynamicSharedMemorySize, GSMEM);

    convert_weights_kernel<<<(CI * C_TOT + 255) / 256, 256>>>(fc1, fc2);
    neocell_bn_kernel<<<dim3(14, 7, 32), 256>>>(x, wa1, wb1, wa2, wb2,
                                                bnw, bnb, bnm, bnv);
    gemm_tn_kernel<256, 1><<<dim3(8, 784), 128, GSMEM>>>(nullptr, nullptr);   // y @ fc1^T, GELU
    gemm_tn_kernel<1024, 2><<<dim3(2, 784), 128, GSMEM>>>(out, x);            // h @ fc2^T + x
}